// round 1
// baseline (speedup 1.0000x reference)
#include <cuda_runtime.h>
#include <cstddef>

// KitNET_5257039970983
// Inputs (metadata order): x(B,100) f32, Wt(10,7,10) f32, hbias_t(10,7) f32,
// vbias_t(10,10) f32, Wh(7,10) f32, hbias_h(7) f32, vbias_h(10) f32, clusters(10,10) i32
// Output: head_out(B,10) followed by tails(B,10), fp32.

#define NTILES 10
#define CDIM   10
#define HDIM   7
#define FDIM   100
#define TPB    256
#define RPB    512          // rows per block (each thread handles rows tid, tid+256)
#define XS_STRIDE 101       // odd stride -> conflict-free per-lane row reads

// ---- shared memory layout (in floats) ----
#define OFF_XS    0
#define OFF_WT2   51712                     // 512*101
#define OFF_HBT2  (OFF_WT2  + 2*NTILES*HDIM*CDIM)   // 51712+1400 = 53112
#define OFF_VBT2  (OFF_HBT2 + 2*NTILES*HDIM)        // 53252
#define OFF_WH2   (OFF_VBT2 + 2*NTILES*CDIM)        // 53452
#define OFF_HBH2  (OFF_WH2  + 2*HDIM*NTILES)        // 53592
#define OFF_VBH2  (OFF_HBH2 + 2*HDIM + 2)           // 53608 (pad 2 -> 16B align)
#define OFF_CL    (OFF_VBH2 + 2*NTILES)             // 53628
#define SMEM_FLOATS (OFF_CL + FDIM)                 // 53728
#define SMEM_BYTES  (SMEM_FLOATS * 4)               // 214912

typedef unsigned long long u64;

__device__ __forceinline__ u64 fma2(u64 a, u64 b, u64 c) {
    u64 d;
    asm("fma.rn.f32x2 %0, %1, %2, %3;" : "=l"(d) : "l"(a), "l"(b), "l"(c));
    return d;
}
__device__ __forceinline__ u64 pack2(float x, float y) {
    u64 d;
    asm("mov.b64 %0, {%1, %2};" : "=l"(d) : "f"(x), "f"(y));
    return d;
}
__device__ __forceinline__ void unpack2(u64 a, float& x, float& y) {
    asm("mov.b64 {%0, %1}, %2;" : "=f"(x), "=f"(y) : "l"(a));
}

__global__ void __launch_bounds__(TPB, 1) kitnet_kernel(
    const float* __restrict__ x,
    const float* __restrict__ Wt,
    const float* __restrict__ hbt,
    const float* __restrict__ vbt,
    const float* __restrict__ Wh,
    const float* __restrict__ hbh,
    const float* __restrict__ vbh,
    const int*   __restrict__ clusters,
    float* __restrict__ out,
    int B)
{
    extern __shared__ float sm[];
    float*  xs   = sm + OFF_XS;
    float2* wt2  = (float2*)(sm + OFF_WT2);
    float2* hbt2 = (float2*)(sm + OFF_HBT2);
    float2* vbt2 = (float2*)(sm + OFF_VBT2);
    float2* wh2  = (float2*)(sm + OFF_WH2);
    float2* hbh2 = (float2*)(sm + OFF_HBH2);
    float2* vbh2 = (float2*)(sm + OFF_VBH2);
    int*    cl   = (int*)(sm + OFF_CL);

    const int tid  = threadIdx.x;
    const int base = blockIdx.x * RPB;
    const int nrows = min(RPB, B - base);

    // ---- stage weights, pre-packed as (w,w) so one load feeds both packed rows ----
    for (int i = tid; i < NTILES*HDIM*CDIM; i += TPB) { float w = Wt[i];  wt2[i]  = make_float2(w, w); }
    for (int i = tid; i < NTILES*HDIM;      i += TPB) { float w = hbt[i]; hbt2[i] = make_float2(w, w); }
    for (int i = tid; i < NTILES*CDIM;      i += TPB) { float w = vbt[i]; vbt2[i] = make_float2(w, w); }
    for (int i = tid; i < HDIM*NTILES;      i += TPB) { float w = Wh[i];  wh2[i]  = make_float2(w, w); }
    if (tid < HDIM)   { float w = hbh[tid]; hbh2[tid] = make_float2(w, w); }
    if (tid < NTILES) { float w = vbh[tid]; vbh2[tid] = make_float2(w, w); }
    for (int i = tid; i < FDIM; i += TPB) cl[i] = clusters[i];

    // ---- stage x: scalar coalesced loads, stride-1 conflict-free STS ----
    {
        const float* xg = x + (size_t)base * FDIM;
        const int ntot = nrows * FDIM;
        #pragma unroll 4
        for (int i = tid; i < ntot; i += TPB) {
            int row = i / FDIM;
            int col = i - row * FDIM;
            xs[row * XS_STRIDE + col] = xg[i];
        }
    }
    __syncthreads();

    const int r0 = base + tid;          // always valid given grid sizing
    const int r1 = base + TPB + tid;    // may be >= B in the last block
    if (r0 >= B) return;

    const float* xr0 = xs + tid * XS_STRIDE;
    const float* xr1 = xs + (TPB + tid) * XS_STRIDE;   // garbage if r1 >= B (never stored)

    const u64 NEG1 = pack2(-1.0f, -1.0f);
    u64 tails[NTILES];

    #pragma unroll 1
    for (int t = 0; t < NTILES; ++t) {
        const int* clt = cl + t * CDIM;
        u64 xc[CDIM];
        #pragma unroll
        for (int c = 0; c < CDIM; ++c) {
            int g = clt[c];
            xc[c] = pack2(xr0[g], xr1[g]);
        }

        const u64* W  = (const u64*)wt2  + t * HDIM * CDIM;
        const u64* hb = (const u64*)hbt2 + t * HDIM;
        const u64* vb = (const u64*)vbt2 + t * CDIM;

        // z[h] = hb[h] + sum_c xc[c] * W[h][c]
        u64 z[HDIM];
        #pragma unroll
        for (int h = 0; h < HDIM; ++h) {
            u64 acc = hb[h];
            #pragma unroll
            for (int cc = 0; cc < CDIM/2; ++cc) {
                ulonglong2 w = *(const ulonglong2*)(W + h*CDIM + 2*cc);
                acc = fma2(xc[2*cc],   w.x, acc);
                acc = fma2(xc[2*cc+1], w.y, acc);
            }
            z[h] = acc;
        }

        // o[c] = (vb[c] - xc[c]) + sum_h z[h] * W[h][c]  == reconstruction error
        u64 o[CDIM];
        #pragma unroll
        for (int c = 0; c < CDIM; ++c) o[c] = fma2(xc[c], NEG1, vb[c]);
        #pragma unroll
        for (int h = 0; h < HDIM; ++h) {
            #pragma unroll
            for (int cc = 0; cc < CDIM/2; ++cc) {
                ulonglong2 w = *(const ulonglong2*)(W + h*CDIM + 2*cc);
                o[2*cc]   = fma2(z[h], w.x, o[2*cc]);
                o[2*cc+1] = fma2(z[h], w.y, o[2*cc+1]);
            }
        }

        u64 err = pack2(0.0f, 0.0f);
        #pragma unroll
        for (int c = 0; c < CDIM; ++c) err = fma2(o[c], o[c], err);

        float e0, e1;
        unpack2(err, e0, e1);
        // log(rmse) = 0.5 * log(mse)
        tails[t] = pack2(0.5f * __logf(e0 * 0.1f), 0.5f * __logf(e1 * 0.1f));
    }

    // ---- head: zh = tails @ Wh.T + hbh ; head_out = zh @ Wh + vbh ----
    const u64* whu = (const u64*)wh2;
    u64 zh[HDIM];
    #pragma unroll
    for (int h = 0; h < HDIM; ++h) {
        u64 acc = ((const u64*)hbh2)[h];
        #pragma unroll
        for (int tt = 0; tt < NTILES/2; ++tt) {
            ulonglong2 w = *(const ulonglong2*)(whu + h*NTILES + 2*tt);
            acc = fma2(tails[2*tt],   w.x, acc);
            acc = fma2(tails[2*tt+1], w.y, acc);
        }
        zh[h] = acc;
    }
    u64 ho[NTILES];
    #pragma unroll
    for (int n = 0; n < NTILES; ++n) ho[n] = ((const u64*)vbh2)[n];
    #pragma unroll
    for (int h = 0; h < HDIM; ++h) {
        #pragma unroll
        for (int nn = 0; nn < NTILES/2; ++nn) {
            ulonglong2 w = *(const ulonglong2*)(whu + h*NTILES + 2*nn);
            ho[2*nn]   = fma2(zh[h], w.x, ho[2*nn]);
            ho[2*nn+1] = fma2(zh[h], w.y, ho[2*nn+1]);
        }
    }

    // ---- stores: head_out at [0, B*10), tails at [B*10, 2*B*10) ----
    const size_t toff = (size_t)B * NTILES;
    float* hop0 = out + (size_t)r0 * NTILES;
    float* tlp0 = out + toff + (size_t)r0 * NTILES;
    const bool v1 = (r1 < B);
    float* hop1 = out + (size_t)r1 * NTILES;
    float* tlp1 = out + toff + (size_t)r1 * NTILES;
    #pragma unroll
    for (int n = 0; n < NTILES; ++n) {
        float a, b2; unpack2(ho[n], a, b2);
        float ta, tb; unpack2(tails[n], ta, tb);
        hop0[n] = a;
        tlp0[n] = ta;
        if (v1) { hop1[n] = b2; tlp1[n] = tb; }
    }
}

extern "C" void kernel_launch(void* const* d_in, const int* in_sizes, int n_in,
                              void* d_out, int out_size)
{
    const float* x   = (const float*)d_in[0];
    const float* Wt  = (const float*)d_in[1];
    const float* hbt = (const float*)d_in[2];
    const float* vbt = (const float*)d_in[3];
    const float* Wh  = (const float*)d_in[4];
    const float* hbh = (const float*)d_in[5];
    const float* vbh = (const float*)d_in[6];
    const int*   cls = (const int*)d_in[7];

    const int B = in_sizes[0] / FDIM;
    const int grid = (B + RPB - 1) / RPB;

    cudaFuncSetAttribute(kitnet_kernel, cudaFuncAttributeMaxDynamicSharedMemorySize, SMEM_BYTES);
    kitnet_kernel<<<grid, TPB, SMEM_BYTES>>>(x, Wt, hbt, vbt, Wh, hbh, vbh, cls,
                                             (float*)d_out, B);
}